// round 1
// baseline (speedup 1.0000x reference)
#include <cuda_runtime.h>
#include <math.h>

#define BB 2
#define SS 2048
#define DIN 4096
#define NH 32
#define NKV 8
#define HD 64
#define QDIM (NH*HD)     // 2048
#define KVDIM (NKV*HD)   // 512
#define DOUT (DIN/2)     // 2048

// Scratch (allocation-free rule: __device__ globals)
__device__ float g_q[BB*SS*QDIM];
__device__ float g_k[BB*SS*KVDIM];
__device__ float g_v[BB*SS*KVDIM];
__device__ float g_o[BB*SS*QDIM];

// ---------------------------------------------------------------------------
// Classic 128x128x8 fp32 SGEMM, 256 threads, 8x8 register micro-tile.
// A: MxK row-major, B: KxN row-major, C: MxN row-major.
// Requires M%128==0, N%128==0, K%8==0 (true for all shapes here).
// ---------------------------------------------------------------------------
__global__ __launch_bounds__(256, 2)
void sgemm_kernel(const float* __restrict__ A, const float* __restrict__ Bm,
                  float* __restrict__ C, int M, int N, int K)
{
    __shared__ float As[8][128];
    __shared__ float Bs[8][128];

    const int tid = threadIdx.x;
    const int bm = blockIdx.y * 128;
    const int bn = blockIdx.x * 128;
    const int tx = tid & 15;
    const int ty = tid >> 4;

    float acc[8][8] = {};

    const int a_i = tid >> 1;          // row within A tile (0..127)
    const int a_k = (tid & 1) * 4;     // k offset (0 or 4)
    const int b_k = tid >> 5;          // row within B tile (0..7)
    const int b_j = (tid & 31) * 4;    // col within B tile

    const float* Aptr = A + (size_t)(bm + a_i) * K + a_k;
    const float* Bptr = Bm + (size_t)b_k * N + bn + b_j;

    for (int k0 = 0; k0 < K; k0 += 8) {
        float4 av = *(const float4*)(Aptr + k0);
        float4 bv = *(const float4*)(Bptr + (size_t)k0 * N);

        As[a_k + 0][a_i] = av.x;
        As[a_k + 1][a_i] = av.y;
        As[a_k + 2][a_i] = av.z;
        As[a_k + 3][a_i] = av.w;
        *(float4*)&Bs[b_k][b_j] = bv;
        __syncthreads();

        #pragma unroll
        for (int kk = 0; kk < 8; kk++) {
            float ar[8], br[8];
            *(float4*)&ar[0] = *(const float4*)&As[kk][ty * 8];
            *(float4*)&ar[4] = *(const float4*)&As[kk][ty * 8 + 4];
            *(float4*)&br[0] = *(const float4*)&Bs[kk][tx * 8];
            *(float4*)&br[4] = *(const float4*)&Bs[kk][tx * 8 + 4];
            #pragma unroll
            for (int i = 0; i < 8; i++)
                #pragma unroll
                for (int j = 0; j < 8; j++)
                    acc[i][j] += ar[i] * br[j];
        }
        __syncthreads();
    }

    #pragma unroll
    for (int i = 0; i < 8; i++) {
        float* crow = C + (size_t)(bm + ty * 8 + i) * N + bn + tx * 8;
        *(float4*)&crow[0] = make_float4(acc[i][0], acc[i][1], acc[i][2], acc[i][3]);
        *(float4*)&crow[4] = make_float4(acc[i][4], acc[i][5], acc[i][6], acc[i][7]);
    }
}

// ---------------------------------------------------------------------------
// RoPE in-place on a (BB*SS, ncols) buffer; ncols = nheads*64.
// Pair (h*64+jp, h*64+jp+32), jp in [0,32).
// ---------------------------------------------------------------------------
__global__ void rope_kernel(float* __restrict__ buf, const int* __restrict__ pos_ids,
                            int ncols)
{
    const int half = ncols >> 1;
    int idx = blockIdx.x * blockDim.x + threadIdx.x;
    int total = BB * SS * half;
    if (idx >= total) return;
    int row = idx / half;
    int pr  = idx - row * half;
    int h  = pr >> 5;
    int jp = pr & 31;
    float pos = (float)pos_ids[row];
    // inv_freq = 10000^(-jp/32) = exp2(-jp/32 * log2(10000))
    float inv = exp2f(-(float)jp * (13.287712379549449f / 32.0f));
    float ang = pos * inv;
    float s, c;
    sincosf(ang, &s, &c);
    float* p1 = buf + (size_t)row * ncols + h * 64 + jp;
    float* p2 = p1 + 32;
    float x1 = *p1, x2 = *p2;
    *p1 = x1 * c - x2 * s;
    *p2 = x2 * c + x1 * s;
}

// ---------------------------------------------------------------------------
// Flash attention, causal, GQA (4 Q heads per KV head).
// Block: one (batch, head, 64-row Q tile). 256 threads.
// Thread t: row r = t/4, 16-wide column/dim slice c0 = (t%4)*16.
// Shared tiles padded to stride 68 (68 mod 32 == 4) to avoid bank conflicts.
// ---------------------------------------------------------------------------
#define PAD 68
__global__ __launch_bounds__(256, 3)
void attn_kernel(const float* __restrict__ q, const float* __restrict__ k,
                 const float* __restrict__ v, float* __restrict__ o)
{
    extern __shared__ float sm[];
    float* q_s     = sm;                  // [64][PAD]
    float* k_sT    = q_s  + 64 * PAD;     // [64][PAD] (dim-major: k_sT[d][c])
    float* v_s     = k_sT + 64 * PAD;     // [64][PAD]
    float* s_s     = v_s  + 64 * PAD;     // [64][PAD] scores / probs
    float* scale_s = s_s  + 64 * PAD;     // [64]
    float* l_s     = scale_s + 64;        // [64]

    const int qt = blockIdx.x;
    const int h  = blockIdx.y;
    const int b  = blockIdx.z;
    const int kvh = h >> 2;

    const int t  = threadIdx.x;
    const int r  = t >> 2;
    const int c0 = (t & 3) << 4;

    // Load Q tile (pre-scaled by 1/sqrt(64))
    const float qscale = 0.125f;
    #pragma unroll
    for (int rep = 0; rep < 4; rep++) {
        int idx = t + rep * 256;            // 0..1023 float4 slots
        int i  = idx >> 4;
        int d4 = (idx & 15) << 2;
        float4 qv = *(const float4*)&q[((size_t)(b * SS + qt * 64 + i)) * QDIM + h * HD + d4];
        float* dst = &q_s[i * PAD + d4];
        dst[0] = qv.x * qscale; dst[1] = qv.y * qscale;
        dst[2] = qv.z * qscale; dst[3] = qv.w * qscale;
    }

    float acc[16];
    #pragma unroll
    for (int i = 0; i < 16; i++) acc[i] = 0.f;
    float m_r = -1e30f, l_r = 0.f;   // valid for t < 64 (row owners)

    const int n_kt = qt + 1;
    const int qi = qt * 64 + r;

    for (int kt = 0; kt < n_kt; kt++) {
        __syncthreads();   // protect k/v/s tiles from previous iteration readers

        // Load K (transposed into k_sT[d][c]) and V tiles
        #pragma unroll
        for (int rep = 0; rep < 4; rep++) {
            int idx = t + rep * 256;
            int c  = idx >> 4;
            int d4 = (idx & 15) << 2;
            size_t base = ((size_t)(b * SS + kt * 64 + c)) * KVDIM + kvh * HD + d4;
            float4 kv = *(const float4*)&k[base];
            k_sT[(d4 + 0) * PAD + c] = kv.x;
            k_sT[(d4 + 1) * PAD + c] = kv.y;
            k_sT[(d4 + 2) * PAD + c] = kv.z;
            k_sT[(d4 + 3) * PAD + c] = kv.w;
            *(float4*)&v_s[c * PAD + d4] = *(const float4*)&v[base];
        }
        __syncthreads();

        // Scores: row r, 16 columns [c0, c0+16)
        float sacc[16];
        #pragma unroll
        for (int i = 0; i < 16; i++) sacc[i] = 0.f;

        #pragma unroll 8
        for (int d = 0; d < 64; d++) {
            float qv = q_s[r * PAD + d];
            const float4* kp = (const float4*)&k_sT[d * PAD + c0];
            float4 k0 = kp[0], k1 = kp[1], k2 = kp[2], k3 = kp[3];
            sacc[0]  += qv * k0.x; sacc[1]  += qv * k0.y; sacc[2]  += qv * k0.z; sacc[3]  += qv * k0.w;
            sacc[4]  += qv * k1.x; sacc[5]  += qv * k1.y; sacc[6]  += qv * k1.z; sacc[7]  += qv * k1.w;
            sacc[8]  += qv * k2.x; sacc[9]  += qv * k2.y; sacc[10] += qv * k2.z; sacc[11] += qv * k2.w;
            sacc[12] += qv * k3.x; sacc[13] += qv * k3.y; sacc[14] += qv * k3.z; sacc[15] += qv * k3.w;
        }
        // causal mask + write to shared
        #pragma unroll
        for (int i = 0; i < 16; i++) {
            int kj = kt * 64 + c0 + i;
            s_s[r * PAD + c0 + i] = (kj <= qi) ? sacc[i] : -1e30f;
        }
        __syncthreads();

        // Online softmax: one owner thread per row
        if (t < 64) {
            float* srow = &s_s[t * PAD];
            float mx = -1e30f;
            #pragma unroll 8
            for (int c = 0; c < 64; c++) mx = fmaxf(mx, srow[c]);
            float new_m = fmaxf(m_r, mx);
            float sum = 0.f;
            #pragma unroll 8
            for (int c = 0; c < 64; c++) {
                float p = __expf(srow[c] - new_m);
                srow[c] = p;
                sum += p;
            }
            float sc = __expf(m_r - new_m);
            l_r = l_r * sc + sum;
            m_r = new_m;
            scale_s[t] = sc;
        }
        __syncthreads();

        // Rescale accumulators and add P*V
        float sc = scale_s[r];
        #pragma unroll
        for (int i = 0; i < 16; i++) acc[i] *= sc;

        #pragma unroll 8
        for (int c = 0; c < 64; c++) {
            float p = s_s[r * PAD + c];
            const float4* vp = (const float4*)&v_s[c * PAD + c0];
            float4 v0 = vp[0], v1 = vp[1], v2 = vp[2], v3 = vp[3];
            acc[0]  += p * v0.x; acc[1]  += p * v0.y; acc[2]  += p * v0.z; acc[3]  += p * v0.w;
            acc[4]  += p * v1.x; acc[5]  += p * v1.y; acc[6]  += p * v1.z; acc[7]  += p * v1.w;
            acc[8]  += p * v2.x; acc[9]  += p * v2.y; acc[10] += p * v2.z; acc[11] += p * v2.w;
            acc[12] += p * v3.x; acc[13] += p * v3.y; acc[14] += p * v3.z; acc[15] += p * v3.w;
        }
    }

    if (t < 64) l_s[t] = l_r;
    __syncthreads();

    float inv_l = 1.0f / l_s[r];
    float* obase = o + ((size_t)(b * SS + qt * 64 + r)) * QDIM + h * HD + c0;
    #pragma unroll
    for (int j = 0; j < 4; j++) {
        *(float4*)&obase[4 * j] = make_float4(acc[4 * j + 0] * inv_l,
                                              acc[4 * j + 1] * inv_l,
                                              acc[4 * j + 2] * inv_l,
                                              acc[4 * j + 3] * inv_l);
    }
}

// ---------------------------------------------------------------------------
extern "C" void kernel_launch(void* const* d_in, const int* in_sizes, int n_in,
                              void* d_out, int out_size)
{
    (void)in_sizes; (void)n_in; (void)out_size;
    const float* hs  = (const float*)d_in[0];
    // d_in[1] = attention_mask (pure causal; handled analytically)
    const int*   pos = (const int*)d_in[2];
    const float* Wq  = (const float*)d_in[3];
    const float* Wk  = (const float*)d_in[4];
    const float* Wv  = (const float*)d_in[5];
    const float* Wo  = (const float*)d_in[6];
    float* out = (float*)d_out;

    float *qb, *kb, *vb, *ob;
    cudaGetSymbolAddress((void**)&qb, g_q);
    cudaGetSymbolAddress((void**)&kb, g_k);
    cudaGetSymbolAddress((void**)&vb, g_v);
    cudaGetSymbolAddress((void**)&ob, g_o);

    const int M = BB * SS;   // 4096

    // QKV projections
    sgemm_kernel<<<dim3(QDIM / 128,  M / 128), 256>>>(hs, Wq, qb, M, QDIM,  DIN);
    sgemm_kernel<<<dim3(KVDIM / 128, M / 128), 256>>>(hs, Wk, kb, M, KVDIM, DIN);
    sgemm_kernel<<<dim3(KVDIM / 128, M / 128), 256>>>(hs, Wv, vb, M, KVDIM, DIN);

    // RoPE
    int nq = M * (QDIM / 2);
    int nk = M * (KVDIM / 2);
    rope_kernel<<<(nq + 255) / 256, 256>>>(qb, pos, QDIM);
    rope_kernel<<<(nk + 255) / 256, 256>>>(kb, pos, KVDIM);

    // Attention
    const int smem = (4 * 64 * PAD + 128) * (int)sizeof(float);  // ~70 KB
    cudaFuncSetAttribute(attn_kernel, cudaFuncAttributeMaxDynamicSharedMemorySize, smem);
    attn_kernel<<<dim3(SS / 64, NH, BB), 256, smem>>>(qb, kb, vb, ob);

    // Output projection
    sgemm_kernel<<<dim3(DOUT / 128, M / 128), 256>>>(ob, Wo, out, M, DOUT, QDIM);
}

// round 3
// speedup vs baseline: 1.4230x; 1.4230x over previous
#include <cuda_runtime.h>
#include <cuda_bf16.h>
#include <math.h>
#include <stdint.h>

#define BB 2
#define SS 2048
#define DIN 4096
#define NH 32
#define NKV 8
#define HD 64
#define QDIM (NH*HD)     // 2048
#define KVDIM (NKV*HD)   // 512
#define DOUT (DIN/2)     // 2048
#define MTOT (BB*SS)     // 4096

// ---------------- scratch (__device__ globals; allocation-free rule) -------
__device__ float g_q[MTOT*QDIM];
__device__ float g_k[MTOT*KVDIM];
__device__ float g_v[MTOT*KVDIM];
__device__ float g_o[MTOT*QDIM];

__device__ __nv_bfloat16 g_hs_hi[MTOT*DIN];
__device__ __nv_bfloat16 g_hs_lo[MTOT*DIN];
__device__ __nv_bfloat16 g_ao_hi[MTOT*QDIM];
__device__ __nv_bfloat16 g_ao_lo[MTOT*QDIM];

// transposed (N x K) bf16 weight splits
__device__ __nv_bfloat16 g_wqT_hi[QDIM*DIN];
__device__ __nv_bfloat16 g_wqT_lo[QDIM*DIN];
__device__ __nv_bfloat16 g_wkT_hi[KVDIM*DIN];
__device__ __nv_bfloat16 g_wkT_lo[KVDIM*DIN];
__device__ __nv_bfloat16 g_wvT_hi[KVDIM*DIN];
__device__ __nv_bfloat16 g_wvT_lo[KVDIM*DIN];
__device__ __nv_bfloat16 g_woT_hi[DOUT*QDIM];
__device__ __nv_bfloat16 g_woT_lo[DOUT*QDIM];

// ---------------- helpers ----------------------------------------------------
__device__ __forceinline__ uint32_t smem_u32(const void* p) {
    uint32_t a;
    asm("{ .reg .u64 t; cvta.to.shared.u64 t, %1; cvt.u32.u64 %0, t; }" : "=r"(a) : "l"(p));
    return a;
}

#define LDSM4(r, addr)                                                           \
    asm volatile("ldmatrix.sync.aligned.m8n8.x4.shared.b16 {%0,%1,%2,%3}, [%4];" \
        : "=r"((r)[0]), "=r"((r)[1]), "=r"((r)[2]), "=r"((r)[3]) : "r"(addr))

#define MMA_BF16(d, a, b0, b1)                                                   \
    asm volatile("mma.sync.aligned.m16n8k16.row.col.f32.bf16.bf16.f32 "          \
        "{%0,%1,%2,%3}, {%4,%5,%6,%7}, {%8,%9}, {%0,%1,%2,%3};"                  \
        : "+f"((d)[0]), "+f"((d)[1]), "+f"((d)[2]), "+f"((d)[3])                 \
        : "r"((a)[0]), "r"((a)[1]), "r"((a)[2]), "r"((a)[3]), "r"(b0), "r"(b1))

#define CP_ASYNC16(dst, src)                                                     \
    asm volatile("cp.async.cg.shared.global [%0], [%1], 16;" :: "r"(dst), "l"(src) : "memory")
#define CP_COMMIT()  asm volatile("cp.async.commit_group;" ::: "memory")
#define CP_WAIT1()   asm volatile("cp.async.wait_group 1;" ::: "memory")
#define CP_WAIT0()   asm volatile("cp.async.wait_group 0;" ::: "memory")

// ---------------- prep kernels ------------------------------------------------
__global__ void split_kernel(const float* __restrict__ x, __nv_bfloat16* __restrict__ hi,
                             __nv_bfloat16* __restrict__ lo, int n4) {
    int i = blockIdx.x * blockDim.x + threadIdx.x;
    if (i >= n4) return;
    float4 v = ((const float4*)x)[i];
    __nv_bfloat16 h[4], l[4];
    float vv[4] = {v.x, v.y, v.z, v.w};
    #pragma unroll
    for (int j = 0; j < 4; j++) {
        h[j] = __float2bfloat16(vv[j]);
        l[j] = __float2bfloat16(vv[j] - __bfloat162float(h[j]));
    }
    ((uint2*)hi)[i] = *(uint2*)h;
    ((uint2*)lo)[i] = *(uint2*)l;
}

// W: K x N row-major  ->  T (N x K) bf16 hi/lo
__global__ void transpose_split_kernel(const float* __restrict__ W,
                                       __nv_bfloat16* __restrict__ Th,
                                       __nv_bfloat16* __restrict__ Tl, int K, int N) {
    __shared__ float t[32][33];
    int k0 = blockIdx.y * 32, n0 = blockIdx.x * 32;
    int x = threadIdx.x, y = threadIdx.y;   // 32 x 8
    #pragma unroll
    for (int i = 0; i < 32; i += 8)
        t[y + i][x] = W[(size_t)(k0 + y + i) * N + n0 + x];
    __syncthreads();
    #pragma unroll
    for (int i = 0; i < 32; i += 8) {
        float v = t[x][y + i];
        __nv_bfloat16 h = __float2bfloat16(v);
        size_t idx = (size_t)(n0 + y + i) * K + k0 + x;
        Th[idx] = h;
        Tl[idx] = __float2bfloat16(v - __bfloat162float(h));
    }
}

// ---------------- split-bf16 HMMA GEMM ----------------------------------------
// C[M,N] = A[M,K] * B^T, Bt is N x K row-major (hi/lo splits), fp32 out.
// CTA 128x128, 8 warps (4 in M x 2 in N), warp tile 32x64.
// K-chunk 32, double-buffered cp.async. Rows padded to 40 bf16 (80B stride).
#define AST 40           // padded row stride in bf16 elems
#define TILE_E (128*AST) // 5120 elems per array
#define STAGE_E (4*TILE_E)
#define GEMM_SMEM (2 * STAGE_E * 2) // bytes = 81920

__device__ __forceinline__ void load_stage(
    uint32_t sbase_bytes, int tid, int bm, int bn, int k0, int K,
    const __nv_bfloat16* __restrict__ Ah, const __nv_bfloat16* __restrict__ Al,
    const __nv_bfloat16* __restrict__ Bh, const __nv_bfloat16* __restrict__ Bl)
{
    #pragma unroll
    for (int i = 0; i < 8; i++) {
        int cid = tid + i * 256;       // 0..2047
        int arr = cid >> 9;            // 0..3
        int rem = cid & 511;
        int row = rem >> 2;            // 0..127
        int c16 = rem & 3;             // 16B chunk within row
        const __nv_bfloat16* g;
        if (arr == 0)      g = Ah + (size_t)(bm + row) * K + k0 + c16 * 8;
        else if (arr == 1) g = Al + (size_t)(bm + row) * K + k0 + c16 * 8;
        else if (arr == 2) g = Bh + (size_t)(bn + row) * K + k0 + c16 * 8;
        else               g = Bl + (size_t)(bn + row) * K + k0 + c16 * 8;
        uint32_t d = sbase_bytes + (uint32_t)(arr * TILE_E + row * AST + c16 * 8) * 2;
        CP_ASYNC16(d, g);
    }
    CP_COMMIT();
}

__global__ __launch_bounds__(256, 1)
void hmma_gemm(const __nv_bfloat16* __restrict__ Ah, const __nv_bfloat16* __restrict__ Al,
               const __nv_bfloat16* __restrict__ Bh, const __nv_bfloat16* __restrict__ Bl,
               float* __restrict__ C, int M, int N, int K)
{
    extern __shared__ __nv_bfloat16 sm[];
    const int tid = threadIdx.x;
    const int wid = tid >> 5;
    const int lane = tid & 31;
    const int bm = blockIdx.y * 128;
    const int bn = blockIdx.x * 128;
    const int wm = (wid & 3) * 32;     // warp M base within tile
    const int wn = (wid >> 2) * 64;    // warp N base within tile

    float acc[2][8][4];
    #pragma unroll
    for (int mt = 0; mt < 2; mt++)
        #pragma unroll
        for (int nt = 0; nt < 8; nt++)
            #pragma unroll
            for (int j = 0; j < 4; j++) acc[mt][nt][j] = 0.f;

    const uint32_t smb = smem_u32(sm);
    const int nch = K >> 5;

    load_stage(smb, tid, bm, bn, 0, K, Ah, Al, Bh, Bl);

    for (int c = 0; c < nch; c++) {
        int buf = c & 1;
        if (c + 1 < nch) {
            load_stage(smb + (uint32_t)(buf ^ 1) * STAGE_E * 2, tid, bm, bn,
                       (c + 1) << 5, K, Ah, Al, Bh, Bl);
            CP_WAIT1();
        } else {
            CP_WAIT0();
        }
        __syncthreads();

        uint32_t Ab  = smb + (uint32_t)buf * STAGE_E * 2;
        uint32_t Alb = Ab + TILE_E * 2;
        uint32_t Bb  = Ab + 2 * TILE_E * 2;
        uint32_t Blb = Ab + 3 * TILE_E * 2;

        #pragma unroll
        for (int ks = 0; ks < 2; ks++) {
            uint32_t ah[2][4], al[2][4], bh[4][4], bl[4][4];
            // A fragments: rows = wm + mt*16 + (lane&15), col = ks*16 + (lane>>4)*8
            #pragma unroll
            for (int mt = 0; mt < 2; mt++) {
                int row = wm + mt * 16 + (lane & 15);
                int col = ks * 16 + ((lane >> 4) << 3);
                uint32_t off = (uint32_t)(row * AST + col) * 2;
                LDSM4(ah[mt], Ab + off);
                LDSM4(al[mt], Alb + off);
            }
            // B fragments: 4 ldmatrix.x4 covering 8 n-tiles
            // lanes 0-7: n rows p*16+0..7 @k0 | 8-15: same rows @k0+8
            // lanes16-23: rows +8 @k0        | 24-31: rows +8 @k0+8
            #pragma unroll
            for (int p = 0; p < 4; p++) {
                int row = wn + p * 16 + (lane & 7) + ((lane >> 4) << 3);
                int col = ks * 16 + (((lane >> 3) & 1) << 3);
                uint32_t off = (uint32_t)(row * AST + col) * 2;
                LDSM4(bh[p], Bb + off);
                LDSM4(bl[p], Blb + off);
            }
            #pragma unroll
            for (int mt = 0; mt < 2; mt++) {
                #pragma unroll
                for (int nt = 0; nt < 8; nt++) {
                    uint32_t b0h = bh[nt >> 1][(nt & 1) * 2];
                    uint32_t b1h = bh[nt >> 1][(nt & 1) * 2 + 1];
                    uint32_t b0l = bl[nt >> 1][(nt & 1) * 2];
                    uint32_t b1l = bl[nt >> 1][(nt & 1) * 2 + 1];
                    MMA_BF16(acc[mt][nt], ah[mt], b0h, b1h);  // hi*hi
                    MMA_BF16(acc[mt][nt], ah[mt], b0l, b1l);  // hi*lo
                    MMA_BF16(acc[mt][nt], al[mt], b0h, b1h);  // lo*hi
                }
            }
        }
        __syncthreads();
    }

    // epilogue
    #pragma unroll
    for (int mt = 0; mt < 2; mt++) {
        #pragma unroll
        for (int nt = 0; nt < 8; nt++) {
            int r0  = bm + wm + mt * 16 + (lane >> 2);
            int col = bn + wn + nt * 8 + (lane & 3) * 2;
            *(float2*)&C[(size_t)r0 * N + col] =
                make_float2(acc[mt][nt][0], acc[mt][nt][1]);
            *(float2*)&C[(size_t)(r0 + 8) * N + col] =
                make_float2(acc[mt][nt][2], acc[mt][nt][3]);
        }
    }
}

// ---------------- RoPE --------------------------------------------------------
__global__ void rope_kernel(float* __restrict__ buf, const int* __restrict__ pos_ids,
                            int ncols)
{
    const int half = ncols >> 1;
    int idx = blockIdx.x * blockDim.x + threadIdx.x;
    int total = BB * SS * half;
    if (idx >= total) return;
    int row = idx / half;
    int pr  = idx - row * half;
    int h  = pr >> 5;
    int jp = pr & 31;
    float pos = (float)pos_ids[row];
    float inv = exp2f(-(float)jp * (13.287712379549449f / 32.0f));
    float ang = pos * inv;
    float s, c;
    sincosf(ang, &s, &c);
    float* p1 = buf + (size_t)row * ncols + h * 64 + jp;
    float* p2 = p1 + 32;
    float x1 = *p1, x2 = *p2;
    *p1 = x1 * c - x2 * s;
    *p2 = x2 * c + x1 * s;
}

// ---------------- flash attention (fp32, known correct) ------------------------
#define PAD 68
__global__ __launch_bounds__(256, 3)
void attn_kernel(const float* __restrict__ q, const float* __restrict__ k,
                 const float* __restrict__ v, float* __restrict__ o)
{
    extern __shared__ float smf[];
    float* q_s     = smf;
    float* k_sT    = q_s  + 64 * PAD;
    float* v_s     = k_sT + 64 * PAD;
    float* s_s     = v_s  + 64 * PAD;
    float* scale_s = s_s  + 64 * PAD;
    float* l_s     = scale_s + 64;

    const int qt = blockIdx.x;
    const int h  = blockIdx.y;
    const int b  = blockIdx.z;
    const int kvh = h >> 2;

    const int t  = threadIdx.x;
    const int r  = t >> 2;
    const int c0 = (t & 3) << 4;

    const float qscale = 0.125f;
    #pragma unroll
    for (int rep = 0; rep < 4; rep++) {
        int idx = t + rep * 256;
        int i  = idx >> 4;
        int d4 = (idx & 15) << 2;
        float4 qv = *(const float4*)&q[((size_t)(b * SS + qt * 64 + i)) * QDIM + h * HD + d4];
        float* dst = &q_s[i * PAD + d4];
        dst[0] = qv.x * qscale; dst[1] = qv.y * qscale;
        dst[2] = qv.z * qscale; dst[3] = qv.w * qscale;
    }

    float acc[16];
    #pragma unroll
    for (int i = 0; i < 16; i++) acc[i] = 0.f;
    float m_r = -1e30f, l_r = 0.f;

    const int n_kt = qt + 1;
    const int qi = qt * 64 + r;

    for (int kt = 0; kt < n_kt; kt++) {
        __syncthreads();

        #pragma unroll
        for (int rep = 0; rep < 4; rep++) {
            int idx = t + rep * 256;
            int c  = idx >> 4;
            int d4 = (idx & 15) << 2;
            size_t base = ((size_t)(b * SS + kt * 64 + c)) * KVDIM + kvh * HD + d4;
            float4 kv = *(const float4*)&k[base];
            k_sT[(d4 + 0) * PAD + c] = kv.x;
            k_sT[(d4 + 1) * PAD + c] = kv.y;
            k_sT[(d4 + 2) * PAD + c] = kv.z;
            k_sT[(d4 + 3) * PAD + c] = kv.w;
            *(float4*)&v_s[c * PAD + d4] = *(const float4*)&v[base];
        }
        __syncthreads();

        float sacc[16];
        #pragma unroll
        for (int i = 0; i < 16; i++) sacc[i] = 0.f;

        #pragma unroll 8
        for (int d = 0; d < 64; d++) {
            float qv = q_s[r * PAD + d];
            const float4* kp = (const float4*)&k_sT[d * PAD + c0];
            float4 k0 = kp[0], k1 = kp[1], k2 = kp[2], k3 = kp[3];
            sacc[0]  += qv * k0.x; sacc[1]  += qv * k0.y; sacc[2]  += qv * k0.z; sacc[3]  += qv * k0.w;
            sacc[4]  += qv * k1.x; sacc[5]  += qv * k1.y; sacc[6]  += qv * k1.z; sacc[7]  += qv * k1.w;
            sacc[8]  += qv * k2.x; sacc[9]  += qv * k2.y; sacc[10] += qv * k2.z; sacc[11] += qv * k2.w;
            sacc[12] += qv * k3.x; sacc[13] += qv * k3.y; sacc[14] += qv * k3.z; sacc[15] += qv * k3.w;
        }
        #pragma unroll
        for (int i = 0; i < 16; i++) {
            int kj = kt * 64 + c0 + i;
            s_s[r * PAD + c0 + i] = (kj <= qi) ? sacc[i] : -1e30f;
        }
        __syncthreads();

        if (t < 64) {
            float* srow = &s_s[t * PAD];
            float mx = -1e30f;
            #pragma unroll 8
            for (int c = 0; c < 64; c++) mx = fmaxf(mx, srow[c]);
            float new_m = fmaxf(m_r, mx);
            float sum = 0.f;
            #pragma unroll 8
            for (int c = 0; c < 64; c++) {
                float p = __expf(srow[c] - new_m);
                srow[c] = p;
                sum += p;
            }
            float sc = __expf(m_r - new_m);
            l_r = l_r * sc + sum;
            m_r = new_m;
            scale_s[t] = sc;
        }
        __syncthreads();

        float sc = scale_s[r];
        #pragma unroll
        for (int i = 0; i < 16; i++) acc[i] *= sc;

        #pragma unroll 8
        for (int c = 0; c < 64; c++) {
            float p = s_s[r * PAD + c];
            const float4* vp = (const float4*)&v_s[c * PAD + c0];
            float4 v0 = vp[0], v1 = vp[1], v2 = vp[2], v3 = vp[3];
            acc[0]  += p * v0.x; acc[1]  += p * v0.y; acc[2]  += p * v0.z; acc[3]  += p * v0.w;
            acc[4]  += p * v1.x; acc[5]  += p * v1.y; acc[6]  += p * v1.z; acc[7]  += p * v1.w;
            acc[8]  += p * v2.x; acc[9]  += p * v2.y; acc[10] += p * v2.z; acc[11] += p * v2.w;
            acc[12] += p * v3.x; acc[13] += p * v3.y; acc[14] += p * v3.z; acc[15] += p * v3.w;
        }
    }

    if (t < 64) l_s[t] = l_r;
    __syncthreads();

    float inv_l = 1.0f / l_s[r];
    float* obase = o + ((size_t)(b * SS + qt * 64 + r)) * QDIM + h * HD + c0;
    #pragma unroll
    for (int j = 0; j < 4; j++) {
        *(float4*)&obase[4 * j] = make_float4(acc[4 * j + 0] * inv_l,
                                              acc[4 * j + 1] * inv_l,
                                              acc[4 * j + 2] * inv_l,
                                              acc[4 * j + 3] * inv_l);
    }
}

// ---------------------------------------------------------------------------
extern "C" void kernel_launch(void* const* d_in, const int* in_sizes, int n_in,
                              void* d_out, int out_size)
{
    (void)in_sizes; (void)n_in; (void)out_size;
    const float* hs  = (const float*)d_in[0];
    const int*   pos = (const int*)d_in[2];
    const float* Wq  = (const float*)d_in[3];
    const float* Wk  = (const float*)d_in[4];
    const float* Wv  = (const float*)d_in[5];
    const float* Wo  = (const float*)d_in[6];
    float* out = (float*)d_out;

    float *qb, *kb, *vb, *ob;
    cudaGetSymbolAddress((void**)&qb, g_q);
    cudaGetSymbolAddress((void**)&kb, g_k);
    cudaGetSymbolAddress((void**)&vb, g_v);
    cudaGetSymbolAddress((void**)&ob, g_o);

    __nv_bfloat16 *hsh, *hsl, *aoh, *aol;
    __nv_bfloat16 *wqh, *wql, *wkh, *wkl, *wvh, *wvl, *woh, *wol;
    cudaGetSymbolAddress((void**)&hsh, g_hs_hi);
    cudaGetSymbolAddress((void**)&hsl, g_hs_lo);
    cudaGetSymbolAddress((void**)&aoh, g_ao_hi);
    cudaGetSymbolAddress((void**)&aol, g_ao_lo);
    cudaGetSymbolAddress((void**)&wqh, g_wqT_hi);
    cudaGetSymbolAddress((void**)&wql, g_wqT_lo);
    cudaGetSymbolAddress((void**)&wkh, g_wkT_hi);
    cudaGetSymbolAddress((void**)&wkl, g_wkT_lo);
    cudaGetSymbolAddress((void**)&wvh, g_wvT_hi);
    cudaGetSymbolAddress((void**)&wvl, g_wvT_lo);
    cudaGetSymbolAddress((void**)&woh, g_woT_hi);
    cudaGetSymbolAddress((void**)&wol, g_woT_lo);

    const int M = MTOT;

    // prep: split hidden states, transpose+split weights
    split_kernel<<<(M * DIN / 4 + 255) / 256, 256>>>(hs, hsh, hsl, M * DIN / 4);
    transpose_split_kernel<<<dim3(QDIM / 32,  DIN / 32),  dim3(32, 8)>>>(Wq, wqh, wql, DIN, QDIM);
    transpose_split_kernel<<<dim3(KVDIM / 32, DIN / 32),  dim3(32, 8)>>>(Wk, wkh, wkl, DIN, KVDIM);
    transpose_split_kernel<<<dim3(KVDIM / 32, DIN / 32),  dim3(32, 8)>>>(Wv, wvh, wvl, DIN, KVDIM);
    transpose_split_kernel<<<dim3(DOUT / 32,  QDIM / 32), dim3(32, 8)>>>(Wo, woh, wol, QDIM, DOUT);

    cudaFuncSetAttribute(hmma_gemm, cudaFuncAttributeMaxDynamicSharedMemorySize, GEMM_SMEM);

    // QKV projections (HMMA split-bf16)
    hmma_gemm<<<dim3(QDIM / 128,  M / 128), 256, GEMM_SMEM>>>(hsh, hsl, wqh, wql, qb, M, QDIM,  DIN);
    hmma_gemm<<<dim3(KVDIM / 128, M / 128), 256, GEMM_SMEM>>>(hsh, hsl, wkh, wkl, kb, M, KVDIM, DIN);
    hmma_gemm<<<dim3(KVDIM / 128, M / 128), 256, GEMM_SMEM>>>(hsh, hsl, wvh, wvl, vb, M, KVDIM, DIN);

    // RoPE
    int nq = M * (QDIM / 2);
    int nk = M * (KVDIM / 2);
    rope_kernel<<<(nq + 255) / 256, 256>>>(qb, pos, QDIM);
    rope_kernel<<<(nk + 255) / 256, 256>>>(kb, pos, KVDIM);

    // attention (fp32)
    const int smem = (4 * 64 * PAD + 128) * (int)sizeof(float);
    cudaFuncSetAttribute(attn_kernel, cudaFuncAttributeMaxDynamicSharedMemorySize, smem);
    attn_kernel<<<dim3(SS / 64, NH, BB), 256, smem>>>(qb, kb, vb, ob);

    // split attention output, then O projection (HMMA)
    split_kernel<<<(M * QDIM / 4 + 255) / 256, 256>>>(ob, aoh, aol, M * QDIM / 4);
    hmma_gemm<<<dim3(DOUT / 128, M / 128), 256, GEMM_SMEM>>>(aoh, aol, woh, wol, out, M, DOUT, QDIM);
}